// round 11
// baseline (speedup 1.0000x reference)
#include <cuda_runtime.h>
#include <cuda_fp16.h>
#include <cstdint>

#define UNITS 512
#define N_DOP 128
#define N_INPUT 512
#define MAX_B 65536

#define BM 128
#define BN 128
#define BK 32
#define THREADS 256
#define KSTAGES (N_INPUT / BK)   // 16

// dynamic smem: 3-stage ring of {A 8K | B 8K}
#define NBUF 3
#define BUF_STRIDE 16384
#define OFF_A 0
#define OFF_B 8192
#define SMEM_DYN (NBUF * BUF_STRIDE + 128)

__device__ float g_mult[UNITS];
__device__ float g_fac[N_DOP];
__device__ int   g_act[N_DOP];
__device__ __half g_w16[UNITS * N_INPUT];       // [n][k] = w[k][n] * mult[n]
__device__ __half g_x16[(size_t)MAX_B * N_INPUT];  // fp16 copy of X

__device__ __forceinline__ uint32_t smem_u32(const void* p) {
    uint32_t a;
    asm("{ .reg .u64 t; cvta.to.shared.u64 t, %1; cvt.u32.u64 %0, t; }" : "=r"(a) : "l"(p));
    return a;
}
// 64-byte rows (32 fp16), 16B chunks; conflict-free for ldmatrix & STS (verified R8-R10)
__device__ __forceinline__ uint32_t swz(int row, int chunk) {
    return (uint32_t)(row * 64 + ((chunk ^ ((row >> 1) & 3)) << 4));
}
__device__ __forceinline__ void ldsm4(uint32_t* r, uint32_t addr) {
    asm volatile("ldmatrix.sync.aligned.m8n8.x4.shared.b16 {%0,%1,%2,%3}, [%4];"
                 : "=r"(r[0]), "=r"(r[1]), "=r"(r[2]), "=r"(r[3]) : "r"(addr));
}
__device__ __forceinline__ void cp16(uint32_t dst, const void* src) {
    asm volatile("cp.async.cg.shared.global [%0], [%1], 16;" :: "r"(dst), "l"(src));
}
__device__ __forceinline__ void mma_fp16(float* c, const uint32_t* a, const uint32_t* b) {
    asm volatile(
        "mma.sync.aligned.m16n8k16.row.col.f32.f16.f16.f32 "
        "{%0,%1,%2,%3}, {%4,%5,%6,%7}, {%8,%9}, {%0,%1,%2,%3};"
        : "+f"(c[0]), "+f"(c[1]), "+f"(c[2]), "+f"(c[3])
        : "r"(a[0]), "r"(a[1]), "r"(a[2]), "r"(a[3]), "r"(b[0]), "r"(b[1]));
}
__device__ __forceinline__ uint32_t pack2h(float a, float b) {
    const __half2 h = __floats2half2_rn(a, b);
    return *(const uint32_t*)&h;
}

__device__ __forceinline__ int dop_index(int j) {
    if (j == N_DOP - 1) return UNITS - 1;
    const double step = 510.0 / 127.0;
    return (int)((double)j * step + 1.0);
}

// ---------------------------------------------------------------------------
// xconv: X fp32 -> fp16 (one-time, streaming)
// ---------------------------------------------------------------------------
__global__ void xconv_kernel(const float* __restrict__ x, int n8) {
    const int i = blockIdx.x * blockDim.x + threadIdx.x;   // index of 8-elem group
    if (i < n8) {
        const float4 v0 = ((const float4*)x)[2 * i];
        const float4 v1 = ((const float4*)x)[2 * i + 1];
        ((uint4*)g_x16)[i] = make_uint4(
            pack2h(v0.x, v0.y), pack2h(v0.z, v0.w),
            pack2h(v1.x, v1.y), pack2h(v1.z, v1.w));
    }
}

// ---------------------------------------------------------------------------
// prep_a: 128 blocks, one per dop neuron (validated R9/R10)
// ---------------------------------------------------------------------------
__global__ void prep_a_kernel(const float* __restrict__ w,
                              const float* __restrict__ dop_old,
                              const float* __restrict__ indicator,
                              const int* __restrict__ bc_raw) {
    __shared__ float red[8];
    const int j = blockIdx.x;
    const int d = dop_index(j);
    const int tid = threadIdx.x, lane = tid & 31, wid = tid >> 5;

    float s = 0.0f;
    for (int i = tid; i < N_INPUT; i += blockDim.x)
        s += fabsf(w[i * UNITS + d] - dop_old[i * UNITS + d]);
    #pragma unroll
    for (int o = 16; o > 0; o >>= 1) s += __shfl_xor_sync(0xffffffffu, s, o);
    if (lane == 0) red[wid] = s;
    __syncthreads();
    if (tid == 0) {
        float t = 0.0f;
        #pragma unroll
        for (int q = 0; q < 8; q++) t += red[q];
        float bc;
        {
            int iv = bc_raw[0];
            if (iv >= -1000000 && iv <= 1000000) bc = (float)iv;
            else bc = __int_as_float(iv);
        }
        const float diff = t * (1.0f / (float)N_INPUT);
        g_fac[j] = 1.0f + 10.0f * diff;
        g_act[j] = (diff > 0.0f) && ((bc - indicator[j]) > 2.0f);
    }
}

// ---------------------------------------------------------------------------
// prep_b: build g_mult (two-phase; R3/R9/R10-validated logic)
// ---------------------------------------------------------------------------
__global__ void prep_b_kernel() {
    __shared__ float s_mult[UNITS];
    __shared__ unsigned char s_isdop[UNITS];
    const int tid = threadIdx.x;
    s_mult[tid] = 1.0f;
    s_isdop[tid] = 0;
    __syncthreads();
    if (tid < N_DOP) s_isdop[dop_index(tid)] = 1;
    __syncthreads();
    if (tid < N_DOP) {
        const int d = dop_index(tid);
        const int c = d - 1;
        if (g_act[tid] && !s_isdop[c]) s_mult[c] *= g_fac[tid];
    }
    __syncthreads();
    if (tid < N_DOP) {
        const int d = dop_index(tid);
        const int c = (d + 1) & (UNITS - 1);
        const bool rightok = (d + 1 >= UNITS) ? true : (!s_isdop[d + 1]);
        if (g_act[tid] && rightok) s_mult[c] *= g_fac[tid];
    }
    __syncthreads();
    g_mult[tid] = s_mult[tid];
}

// ---------------------------------------------------------------------------
// prep2: coalesced transpose+scale+fp16 (validated R9/R10)
// ---------------------------------------------------------------------------
__global__ void prep2_kernel(const float* __restrict__ w) {
    __shared__ float tile[32][33];
    const int tx = threadIdx.x, ty = threadIdx.y;
    const int n0 = blockIdx.x * 32, k0 = blockIdx.y * 32;
    tile[ty][tx] = w[(size_t)(k0 + ty) * UNITS + n0 + tx];
    __syncthreads();
    const float m = g_mult[n0 + ty];
    g_w16[(size_t)(n0 + ty) * N_INPUT + k0 + tx] = __float2half_rn(tile[tx][ty] * m);
}

// ---------------------------------------------------------------------------
// GEMM: 256 threads, 8 warps (4M x 2N), warp tile 32x64, all-cp.async, 3-stage ring
// ---------------------------------------------------------------------------
__global__ __launch_bounds__(THREADS, 2)
void gemm_kernel(const float* __restrict__ bias, float* __restrict__ C) {
    extern __shared__ char dsm[];
    __shared__ float sbias[BN];

    const int tid = threadIdx.x, lane = tid & 31, wid = tid >> 5;
    const int bx = blockIdx.x, by = blockIdx.y;
    const uint32_t raw = smem_u32(dsm);
    const uint32_t base = (raw + 127u) & ~127u;

    if (tid < BN) sbias[tid] = bias[bx * BN + tid];

    const int warp_m = wid & 3;      // 4 warps in M (32 rows each)
    const int warp_n = wid >> 2;     // 2 warps in N (64 cols each)

    // loader: 2 slots of 16B chunks per thread per matrix
    const int r0_ = tid >> 2, c0_ = tid & 3;          // slot 0: rows 0..63
    const int r1_ = r0_ + 64, c1_ = c0_;              // slot 1: rows 64..127
    const uint32_t sts0 = swz(r0_, c0_), sts1 = swz(r1_, c1_);
    const __half* gA0 = g_x16 + ((size_t)by * BM + r0_) * N_INPUT + c0_ * 8;
    const __half* gA1 = g_x16 + ((size_t)by * BM + r1_) * N_INPUT + c1_ * 8;
    const __half* gB0 = g_w16 + ((size_t)bx * BN + r0_) * N_INPUT + c0_ * 8;
    const __half* gB1 = g_w16 + ((size_t)bx * BN + r1_) * N_INPUT + c1_ * 8;

    float acc[2][8][4];
    #pragma unroll
    for (int mt = 0; mt < 2; mt++)
        #pragma unroll
        for (int nt = 0; nt < 8; nt++)
            #pragma unroll
            for (int q = 0; q < 4; q++) acc[mt][nt][q] = 0.0f;

    // ---- prologue: issue stages 0 and 1 ----
    #pragma unroll
    for (int s = 0; s < 2; s++) {
        const uint32_t bb = base + s * BUF_STRIDE;
        const int ko = s * BK;
        cp16(bb + OFF_A + sts0, gA0 + ko);
        cp16(bb + OFF_A + sts1, gA1 + ko);
        cp16(bb + OFF_B + sts0, gB0 + ko);
        cp16(bb + OFF_B + sts1, gB1 + ko);
        asm volatile("cp.async.commit_group;" ::: "memory");
    }

    int bufidx = 0;
    for (int s = 0; s < KSTAGES; s++) {
        // stage s must be complete: allow 1 newer group outstanding (0 at tail)
        if (s < KSTAGES - 2) {
            asm volatile("cp.async.wait_group 1;" ::: "memory");
        } else {
            asm volatile("cp.async.wait_group 0;" ::: "memory");
        }
        __syncthreads();

        // prefetch stage s+2 into the buffer freed by stage s-1
        if (s + 2 < KSTAGES) {
            int pi = bufidx + 2; if (pi >= NBUF) pi -= NBUF;
            const uint32_t bb = base + pi * BUF_STRIDE;
            const int ko = (s + 2) * BK;
            cp16(bb + OFF_A + sts0, gA0 + ko);
            cp16(bb + OFF_A + sts1, gA1 + ko);
            cp16(bb + OFF_B + sts0, gB0 + ko);
            cp16(bb + OFF_B + sts1, gB1 + ko);
            asm volatile("cp.async.commit_group;" ::: "memory");
        }

        const uint32_t cb = base + bufidx * BUF_STRIDE;
        #pragma unroll
        for (int ks = 0; ks < 2; ks++) {
            uint32_t ah[2][4], bh[8][2];
            #pragma unroll
            for (int mt = 0; mt < 2; mt++) {
                const int row = warp_m * 32 + mt * 16 + (lane & 15);
                const int ch  = ks * 2 + (lane >> 4);
                ldsm4(ah[mt], cb + OFF_A + swz(row, ch));
            }
            #pragma unroll
            for (int np = 0; np < 4; np++) {
                const int g = lane >> 3;
                const int row = warp_n * 64 + (np * 2 + (g >> 1)) * 8 + (lane & 7);
                const int ch  = ks * 2 + (g & 1);
                uint32_t r[4];
                ldsm4(r, cb + OFF_B + swz(row, ch));
                bh[np * 2 + 0][0] = r[0]; bh[np * 2 + 0][1] = r[1];
                bh[np * 2 + 1][0] = r[2]; bh[np * 2 + 1][1] = r[3];
            }
            #pragma unroll
            for (int mt = 0; mt < 2; mt++)
                #pragma unroll
                for (int nt = 0; nt < 8; nt++)
                    mma_fp16(acc[mt][nt], ah[mt], bh[nt]);
        }

        bufidx++; if (bufidx >= NBUF) bufidx -= NBUF;
    }

    // ---- epilogue: bias + relu, float2 stores ----
    const int gq = lane >> 2, tq = lane & 3;
    #pragma unroll
    for (int mt = 0; mt < 2; mt++) {
        const int r0 = warp_m * 32 + mt * 16 + gq;
        float* crow0 = C + ((size_t)by * BM + r0) * UNITS + bx * BN;
        float* crow1 = crow0 + 8 * UNITS;
        #pragma unroll
        for (int nt = 0; nt < 8; nt++) {
            const int col = warp_n * 64 + nt * 8 + tq * 2;
            float2 o0, o1;
            o0.x = fmaxf(acc[mt][nt][0] + sbias[col], 0.0f);
            o0.y = fmaxf(acc[mt][nt][1] + sbias[col + 1], 0.0f);
            o1.x = fmaxf(acc[mt][nt][2] + sbias[col], 0.0f);
            o1.y = fmaxf(acc[mt][nt][3] + sbias[col + 1], 0.0f);
            *(float2*)(crow0 + col) = o0;
            *(float2*)(crow1 + col) = o1;
        }
    }
}

extern "C" void kernel_launch(void* const* d_in, const int* in_sizes, int n_in,
                              void* d_out, int out_size) {
    const float* x   = (const float*)d_in[0];
    const float* w   = (const float*)d_in[1];
    const float* b   = (const float*)d_in[2];
    const float* old = (const float*)d_in[3];
    const float* ind = (const float*)d_in[4];
    const int*   bc  = (const int*)d_in[5];

    const int M = in_sizes[0] / N_INPUT;

    cudaFuncSetAttribute(gemm_kernel, cudaFuncAttributeMaxDynamicSharedMemorySize, SMEM_DYN);

    const int n8 = M * N_INPUT / 8;
    xconv_kernel<<<(n8 + 255) / 256, 256>>>(x, n8);
    prep_a_kernel<<<N_DOP, 256>>>(w, old, ind, bc);
    prep_b_kernel<<<1, UNITS>>>();
    dim3 tgrid(UNITS / 32, N_INPUT / 32);
    prep2_kernel<<<tgrid, dim3(32, 32)>>>(w);
    dim3 grid(UNITS / BN, M / BM);
    gemm_kernel<<<grid, THREADS, SMEM_DYN>>>(b, (float*)d_out);
}

// round 13
// speedup vs baseline: 1.0707x; 1.0707x over previous
#include <cuda_runtime.h>
#include <cuda_fp16.h>
#include <cstdint>

#define UNITS 512
#define N_DOP 128
#define N_INPUT 512
#define MAX_B 65536

#define BM 128
#define BN 128
#define BK 64
#define THREADS 256
#define KSTAGES (N_INPUT / BK)   // 8

// dynamic smem: 3-stage ring of {A 16K | B 16K}
#define NBUF 3
#define BUF_STRIDE 32768
#define OFF_A 0
#define OFF_B 16384
#define SMEM_DYN (NBUF * BUF_STRIDE + 128)

__device__ float g_mult[UNITS];
__device__ float g_fac[N_DOP];
__device__ int   g_act[N_DOP];
__device__ __half g_w16[UNITS * N_INPUT];          // [n][k] = w[k][n] * mult[n]
__device__ __half g_x16[(size_t)MAX_B * N_INPUT];  // fp16 copy of X

__device__ __forceinline__ uint32_t smem_u32(const void* p) {
    uint32_t a;
    asm("{ .reg .u64 t; cvta.to.shared.u64 t, %1; cvt.u32.u64 %0, t; }" : "=r"(a) : "l"(p));
    return a;
}
// 128-byte rows (64 fp16), 8 chunks of 16B; per-row bijective chunk permutation
__device__ __forceinline__ uint32_t swz(int row, int ch) {
    return (uint32_t)(row * 128 + ((ch ^ (row & 7)) << 4));
}
__device__ __forceinline__ void ldsm4(uint32_t* r, uint32_t addr) {
    asm volatile("ldmatrix.sync.aligned.m8n8.x4.shared.b16 {%0,%1,%2,%3}, [%4];"
                 : "=r"(r[0]), "=r"(r[1]), "=r"(r[2]), "=r"(r[3]) : "r"(addr));
}
__device__ __forceinline__ void cp16(uint32_t dst, const void* src) {
    asm volatile("cp.async.cg.shared.global [%0], [%1], 16;" :: "r"(dst), "l"(src));
}
__device__ __forceinline__ void mma_fp16(float* c, const uint32_t* a, const uint32_t* b) {
    asm volatile(
        "mma.sync.aligned.m16n8k16.row.col.f32.f16.f16.f32 "
        "{%0,%1,%2,%3}, {%4,%5,%6,%7}, {%8,%9}, {%0,%1,%2,%3};"
        : "+f"(c[0]), "+f"(c[1]), "+f"(c[2]), "+f"(c[3])
        : "r"(a[0]), "r"(a[1]), "r"(a[2]), "r"(a[3]), "r"(b[0]), "r"(b[1]));
}
__device__ __forceinline__ uint32_t pack2h(float a, float b) {
    const __half2 h = __floats2half2_rn(a, b);
    return *(const uint32_t*)&h;
}

__device__ __forceinline__ int dop_index(int j) {
    if (j == N_DOP - 1) return UNITS - 1;
    const double step = 510.0 / 127.0;
    return (int)((double)j * step + 1.0);
}

// ---------------------------------------------------------------------------
// xconv: X fp32 -> fp16 (one-time, streaming)
// ---------------------------------------------------------------------------
__global__ void xconv_kernel(const float* __restrict__ x, int n8) {
    const int i = blockIdx.x * blockDim.x + threadIdx.x;
    if (i < n8) {
        const float4 v0 = ((const float4*)x)[2 * i];
        const float4 v1 = ((const float4*)x)[2 * i + 1];
        ((uint4*)g_x16)[i] = make_uint4(
            pack2h(v0.x, v0.y), pack2h(v0.z, v0.w),
            pack2h(v1.x, v1.y), pack2h(v1.z, v1.w));
    }
}

// ---------------------------------------------------------------------------
// prep_a: 128 blocks, one per dop neuron (validated R9-R11)
// ---------------------------------------------------------------------------
__global__ void prep_a_kernel(const float* __restrict__ w,
                              const float* __restrict__ dop_old,
                              const float* __restrict__ indicator,
                              const int* __restrict__ bc_raw) {
    __shared__ float red[8];
    const int j = blockIdx.x;
    const int d = dop_index(j);
    const int tid = threadIdx.x, lane = tid & 31, wid = tid >> 5;

    float s = 0.0f;
    for (int i = tid; i < N_INPUT; i += blockDim.x)
        s += fabsf(w[i * UNITS + d] - dop_old[i * UNITS + d]);
    #pragma unroll
    for (int o = 16; o > 0; o >>= 1) s += __shfl_xor_sync(0xffffffffu, s, o);
    if (lane == 0) red[wid] = s;
    __syncthreads();
    if (tid == 0) {
        float t = 0.0f;
        #pragma unroll
        for (int q = 0; q < 8; q++) t += red[q];
        float bc;
        {
            int iv = bc_raw[0];
            if (iv >= -1000000 && iv <= 1000000) bc = (float)iv;
            else bc = __int_as_float(iv);
        }
        const float diff = t * (1.0f / (float)N_INPUT);
        g_fac[j] = 1.0f + 10.0f * diff;
        g_act[j] = (diff > 0.0f) && ((bc - indicator[j]) > 2.0f);
    }
}

// ---------------------------------------------------------------------------
// prep_b: build g_mult (two-phase; validated R3/R9-R11)
// ---------------------------------------------------------------------------
__global__ void prep_b_kernel() {
    __shared__ float s_mult[UNITS];
    __shared__ unsigned char s_isdop[UNITS];
    const int tid = threadIdx.x;
    s_mult[tid] = 1.0f;
    s_isdop[tid] = 0;
    __syncthreads();
    if (tid < N_DOP) s_isdop[dop_index(tid)] = 1;
    __syncthreads();
    if (tid < N_DOP) {
        const int d = dop_index(tid);
        const int c = d - 1;
        if (g_act[tid] && !s_isdop[c]) s_mult[c] *= g_fac[tid];
    }
    __syncthreads();
    if (tid < N_DOP) {
        const int d = dop_index(tid);
        const int c = (d + 1) & (UNITS - 1);
        const bool rightok = (d + 1 >= UNITS) ? true : (!s_isdop[d + 1]);
        if (g_act[tid] && rightok) s_mult[c] *= g_fac[tid];
    }
    __syncthreads();
    g_mult[tid] = s_mult[tid];
}

// ---------------------------------------------------------------------------
// prep2: coalesced transpose+scale+fp16 (validated R9-R11)
// ---------------------------------------------------------------------------
__global__ void prep2_kernel(const float* __restrict__ w) {
    __shared__ float tile[32][33];
    const int tx = threadIdx.x, ty = threadIdx.y;
    const int n0 = blockIdx.x * 32, k0 = blockIdx.y * 32;
    tile[ty][tx] = w[(size_t)(k0 + ty) * UNITS + n0 + tx];
    __syncthreads();
    const float m = g_mult[n0 + ty];
    g_w16[(size_t)(n0 + ty) * N_INPUT + k0 + tx] = __float2half_rn(tile[tx][ty] * m);
}

// ---------------------------------------------------------------------------
// GEMM: 256 threads, 8 warps (4M x 2N), warp tile 32x64, BK=64, 3-stage ring
// ---------------------------------------------------------------------------
__global__ __launch_bounds__(THREADS, 2)
void gemm_kernel(const float* __restrict__ bias, float* __restrict__ C) {
    extern __shared__ char dsm[];
    __shared__ float sbias[BN];

    const int tid = threadIdx.x, lane = tid & 31, wid = tid >> 5;
    const int bx = blockIdx.x, by = blockIdx.y;
    const uint32_t raw = smem_u32(dsm);
    const uint32_t base = (raw + 127u) & ~127u;

    if (tid < BN) sbias[tid] = bias[bx * BN + tid];

    const int warp_m = wid & 3;      // 4 warps in M (32 rows each)
    const int warp_n = wid >> 2;     // 2 warps in N (64 cols each)

    const __half* gA = g_x16 + (size_t)by * BM * N_INPUT;
    const __half* gB = g_w16 + (size_t)bx * BN * N_INPUT;

    float acc[2][8][4];
    #pragma unroll
    for (int mt = 0; mt < 2; mt++)
        #pragma unroll
        for (int nt = 0; nt < 8; nt++)
            #pragma unroll
            for (int q = 0; q < 4; q++) acc[mt][nt][q] = 0.0f;

    // ---- prologue: issue stages 0 and 1 ----
    #pragma unroll
    for (int s = 0; s < 2; s++) {
        const uint32_t bb = base + s * BUF_STRIDE;
        #pragma unroll
        for (int i = 0; i < 4; i++) {
            const int idx = tid + i * 256;
            const int row = idx >> 3, ch = idx & 7;
            const size_t go = (size_t)row * N_INPUT + s * BK + ch * 8;
            const uint32_t so = swz(row, ch);
            cp16(bb + OFF_A + so, gA + go);
            cp16(bb + OFF_B + so, gB + go);
        }
        asm volatile("cp.async.commit_group;" ::: "memory");
    }

    int bufidx = 0;
    for (int s = 0; s < KSTAGES; s++) {
        if (s < KSTAGES - 2) {
            asm volatile("cp.async.wait_group 1;" ::: "memory");
        } else {
            asm volatile("cp.async.wait_group 0;" ::: "memory");
        }
        __syncthreads();

        if (s + 2 < KSTAGES) {
            int pi = bufidx + 2; if (pi >= NBUF) pi -= NBUF;
            const uint32_t bb = base + pi * BUF_STRIDE;
            #pragma unroll
            for (int i = 0; i < 4; i++) {
                const int idx = tid + i * 256;
                const int row = idx >> 3, ch = idx & 7;
                const size_t go = (size_t)row * N_INPUT + (s + 2) * BK + ch * 8;
                const uint32_t so = swz(row, ch);
                cp16(bb + OFF_A + so, gA + go);
                cp16(bb + OFF_B + so, gB + go);
            }
            asm volatile("cp.async.commit_group;" ::: "memory");
        }

        const uint32_t cb = base + bufidx * BUF_STRIDE;
        #pragma unroll
        for (int ks = 0; ks < 4; ks++) {
            uint32_t ah[2][4], bh[8][2];
            #pragma unroll
            for (int mt = 0; mt < 2; mt++) {
                const int row = warp_m * 32 + mt * 16 + (lane & 15);
                const int ch  = ks * 2 + (lane >> 4);
                ldsm4(ah[mt], cb + OFF_A + swz(row, ch));
            }
            #pragma unroll
            for (int np = 0; np < 4; np++) {
                const int g = lane >> 3;
                const int row = warp_n * 64 + (np * 2 + (g >> 1)) * 8 + (lane & 7);
                const int ch  = ks * 2 + (g & 1);
                uint32_t r[4];
                ldsm4(r, cb + OFF_B + swz(row, ch));
                bh[np * 2 + 0][0] = r[0]; bh[np * 2 + 0][1] = r[1];
                bh[np * 2 + 1][0] = r[2]; bh[np * 2 + 1][1] = r[3];
            }
            #pragma unroll
            for (int mt = 0; mt < 2; mt++)
                #pragma unroll
                for (int nt = 0; nt < 8; nt++)
                    mma_fp16(acc[mt][nt], ah[mt], bh[nt]);
        }

        bufidx++; if (bufidx >= NBUF) bufidx -= NBUF;
    }

    // ---- epilogue: bias + relu, float2 stores ----
    const int gq = lane >> 2, tq = lane & 3;
    #pragma unroll
    for (int mt = 0; mt < 2; mt++) {
        const int r0 = warp_m * 32 + mt * 16 + gq;
        float* crow0 = C + ((size_t)by * BM + r0) * UNITS + bx * BN;
        float* crow1 = crow0 + 8 * UNITS;
        #pragma unroll
        for (int nt = 0; nt < 8; nt++) {
            const int col = warp_n * 64 + nt * 8 + tq * 2;
            float2 o0, o1;
            o0.x = fmaxf(acc[mt][nt][0] + sbias[col], 0.0f);
            o0.y = fmaxf(acc[mt][nt][1] + sbias[col + 1], 0.0f);
            o1.x = fmaxf(acc[mt][nt][2] + sbias[col], 0.0f);
            o1.y = fmaxf(acc[mt][nt][3] + sbias[col + 1], 0.0f);
            *(float2*)(crow0 + col) = o0;
            *(float2*)(crow1 + col) = o1;
        }
    }
}

extern "C" void kernel_launch(void* const* d_in, const int* in_sizes, int n_in,
                              void* d_out, int out_size) {
    const float* x   = (const float*)d_in[0];
    const float* w   = (const float*)d_in[1];
    const float* b   = (const float*)d_in[2];
    const float* old = (const float*)d_in[3];
    const float* ind = (const float*)d_in[4];
    const int*   bc  = (const int*)d_in[5];

    const int M = in_sizes[0] / N_INPUT;

    cudaFuncSetAttribute(gemm_kernel, cudaFuncAttributeMaxDynamicSharedMemorySize, SMEM_DYN);

    const int n8 = M * N_INPUT / 8;
    xconv_kernel<<<(n8 + 255) / 256, 256>>>(x, n8);
    prep_a_kernel<<<N_DOP, 256>>>(w, old, ind, bc);
    prep_b_kernel<<<1, UNITS>>>();
    dim3 tgrid(UNITS / 32, N_INPUT / 32);
    prep2_kernel<<<tgrid, dim3(32, 32)>>>(w);
    dim3 grid(UNITS / BN, M / BM);
    gemm_kernel<<<grid, THREADS, SMEM_DYN>>>(b, (float*)d_out);
}

// round 14
// speedup vs baseline: 1.1005x; 1.0278x over previous
#include <cuda_runtime.h>
#include <cuda_fp16.h>
#include <cstdint>

#define UNITS 512
#define N_DOP 128
#define N_INPUT 512
#define MAX_B 65536

#define BM 128
#define BN 128
#define BK 64
#define THREADS 256
#define KSTAGES (N_INPUT / BK)   // 8

// dynamic smem: 3-stage ring of {A 16K | B 16K}
#define NBUF 3
#define BUF_STRIDE 32768
#define OFF_A 0
#define OFF_B 16384
#define SMEM_DYN (NBUF * BUF_STRIDE + 128)

__device__ float g_mult[UNITS];
__device__ float g_fac[N_DOP];
__device__ int   g_act[N_DOP];
__device__ __half g_w16[UNITS * N_INPUT];          // [n][k] = w[k][n] * mult[n]
__device__ __half g_x16[(size_t)MAX_B * N_INPUT];  // fp16 copy of X

__device__ __forceinline__ uint32_t smem_u32(const void* p) {
    uint32_t a;
    asm("{ .reg .u64 t; cvta.to.shared.u64 t, %1; cvt.u32.u64 %0, t; }" : "=r"(a) : "l"(p));
    return a;
}
// 128-byte rows (64 fp16), 8 chunks of 16B; per-row bijective chunk permutation
__device__ __forceinline__ uint32_t swz(int row, int ch) {
    return (uint32_t)(row * 128 + ((ch ^ (row & 7)) << 4));
}
__device__ __forceinline__ void ldsm4(uint32_t* r, uint32_t addr) {
    asm volatile("ldmatrix.sync.aligned.m8n8.x4.shared.b16 {%0,%1,%2,%3}, [%4];"
                 : "=r"(r[0]), "=r"(r[1]), "=r"(r[2]), "=r"(r[3]) : "r"(addr));
}
__device__ __forceinline__ void cp16(uint32_t dst, const void* src) {
    asm volatile("cp.async.cg.shared.global [%0], [%1], 16;" :: "r"(dst), "l"(src));
}
__device__ __forceinline__ void mma_fp16(float* c, const uint32_t* a, const uint32_t* b) {
    asm volatile(
        "mma.sync.aligned.m16n8k16.row.col.f32.f16.f16.f32 "
        "{%0,%1,%2,%3}, {%4,%5,%6,%7}, {%8,%9}, {%0,%1,%2,%3};"
        : "+f"(c[0]), "+f"(c[1]), "+f"(c[2]), "+f"(c[3])
        : "r"(a[0]), "r"(a[1]), "r"(a[2]), "r"(a[3]), "r"(b[0]), "r"(b[1]));
}
__device__ __forceinline__ uint32_t pack2h(float a, float b) {
    const __half2 h = __floats2half2_rn(a, b);
    return *(const uint32_t*)&h;
}

__device__ __forceinline__ int dop_index(int j) {
    if (j == N_DOP - 1) return UNITS - 1;
    const double step = 510.0 / 127.0;
    return (int)((double)j * step + 1.0);
}

// ---------------------------------------------------------------------------
// k1: fused prep_a (blocks 0..127) + xconv (blocks 128..) — independent work,
// runs concurrently in one grid. Both use 256-thread blocks.
// ---------------------------------------------------------------------------
__global__ void k1_kernel(const float* __restrict__ w,
                          const float* __restrict__ dop_old,
                          const float* __restrict__ indicator,
                          const int* __restrict__ bc_raw,
                          const float* __restrict__ x, int n8) {
    if (blockIdx.x < N_DOP) {
        // ---- prep_a ----
        __shared__ float red[8];
        const int j = blockIdx.x;
        const int d = dop_index(j);
        const int tid = threadIdx.x, lane = tid & 31, wid = tid >> 5;

        float s = 0.0f;
        for (int i = tid; i < N_INPUT; i += blockDim.x)
            s += fabsf(w[i * UNITS + d] - dop_old[i * UNITS + d]);
        #pragma unroll
        for (int o = 16; o > 0; o >>= 1) s += __shfl_xor_sync(0xffffffffu, s, o);
        if (lane == 0) red[wid] = s;
        __syncthreads();
        if (tid == 0) {
            float t = 0.0f;
            #pragma unroll
            for (int q = 0; q < 8; q++) t += red[q];
            float bc;
            {
                int iv = bc_raw[0];
                if (iv >= -1000000 && iv <= 1000000) bc = (float)iv;
                else bc = __int_as_float(iv);
            }
            const float diff = t * (1.0f / (float)N_INPUT);
            g_fac[j] = 1.0f + 10.0f * diff;
            g_act[j] = (diff > 0.0f) && ((bc - indicator[j]) > 2.0f);
        }
    } else {
        // ---- xconv ----
        const int i = (blockIdx.x - N_DOP) * blockDim.x + threadIdx.x;
        if (i < n8) {
            const float4 v0 = ((const float4*)x)[2 * i];
            const float4 v1 = ((const float4*)x)[2 * i + 1];
            ((uint4*)g_x16)[i] = make_uint4(
                pack2h(v0.x, v0.y), pack2h(v0.z, v0.w),
                pack2h(v1.x, v1.y), pack2h(v1.z, v1.w));
        }
    }
}

// ---------------------------------------------------------------------------
// prep_b: build g_mult (two-phase; validated R3/R9-R13)
// ---------------------------------------------------------------------------
__global__ void prep_b_kernel() {
    __shared__ float s_mult[UNITS];
    __shared__ unsigned char s_isdop[UNITS];
    const int tid = threadIdx.x;
    s_mult[tid] = 1.0f;
    s_isdop[tid] = 0;
    __syncthreads();
    if (tid < N_DOP) s_isdop[dop_index(tid)] = 1;
    __syncthreads();
    if (tid < N_DOP) {
        const int d = dop_index(tid);
        const int c = d - 1;
        if (g_act[tid] && !s_isdop[c]) s_mult[c] *= g_fac[tid];
    }
    __syncthreads();
    if (tid < N_DOP) {
        const int d = dop_index(tid);
        const int c = (d + 1) & (UNITS - 1);
        const bool rightok = (d + 1 >= UNITS) ? true : (!s_isdop[d + 1]);
        if (g_act[tid] && rightok) s_mult[c] *= g_fac[tid];
    }
    __syncthreads();
    g_mult[tid] = s_mult[tid];
}

// ---------------------------------------------------------------------------
// prep2: coalesced transpose+scale+fp16 (validated R9-R13)
// ---------------------------------------------------------------------------
__global__ void prep2_kernel(const float* __restrict__ w) {
    __shared__ float tile[32][33];
    const int tx = threadIdx.x, ty = threadIdx.y;
    const int n0 = blockIdx.x * 32, k0 = blockIdx.y * 32;
    tile[ty][tx] = w[(size_t)(k0 + ty) * UNITS + n0 + tx];
    __syncthreads();
    const float m = g_mult[n0 + ty];
    g_w16[(size_t)(n0 + ty) * N_INPUT + k0 + tx] = __float2half_rn(tile[tx][ty] * m);
}

// load one k16-step's fragments (2 ldsm4 A + 4 ldsm4 B)
#define LOAD_FRAGS(ksv, AH, BH) do {                                           \
    _Pragma("unroll")                                                          \
    for (int mt = 0; mt < 2; mt++) {                                           \
        const int row = warp_m * 32 + mt * 16 + (lane & 15);                   \
        const int ch  = (ksv) * 2 + (lane >> 4);                               \
        ldsm4(AH[mt], cb + OFF_A + swz(row, ch));                              \
    }                                                                          \
    _Pragma("unroll")                                                          \
    for (int np = 0; np < 4; np++) {                                           \
        const int g = lane >> 3;                                               \
        const int row = warp_n * 64 + (np * 2 + (g >> 1)) * 8 + (lane & 7);    \
        const int ch  = (ksv) * 2 + (g & 1);                                   \
        uint32_t r[4];                                                         \
        ldsm4(r, cb + OFF_B + swz(row, ch));                                   \
        BH[np * 2 + 0][0] = r[0]; BH[np * 2 + 0][1] = r[1];                    \
        BH[np * 2 + 1][0] = r[2]; BH[np * 2 + 1][1] = r[3];                    \
    }                                                                          \
} while (0)

// ---------------------------------------------------------------------------
// GEMM: 256 threads, 8 warps (4M x 2N), warp tile 32x64, BK=64, 3-stage ring,
// fragment-level software pipeline (double-buffered ldsm)
// ---------------------------------------------------------------------------
__global__ __launch_bounds__(THREADS, 2)
void gemm_kernel(const float* __restrict__ bias, float* __restrict__ C) {
    extern __shared__ char dsm[];
    __shared__ float sbias[BN];

    const int tid = threadIdx.x, lane = tid & 31, wid = tid >> 5;
    const int bx = blockIdx.x, by = blockIdx.y;
    const uint32_t raw = smem_u32(dsm);
    const uint32_t base = (raw + 127u) & ~127u;

    if (tid < BN) sbias[tid] = bias[bx * BN + tid];

    const int warp_m = wid & 3;      // 4 warps in M (32 rows each)
    const int warp_n = wid >> 2;     // 2 warps in N (64 cols each)

    const __half* gA = g_x16 + (size_t)by * BM * N_INPUT;
    const __half* gB = g_w16 + (size_t)bx * BN * N_INPUT;

    float acc[2][8][4];
    #pragma unroll
    for (int mt = 0; mt < 2; mt++)
        #pragma unroll
        for (int nt = 0; nt < 8; nt++)
            #pragma unroll
            for (int q = 0; q < 4; q++) acc[mt][nt][q] = 0.0f;

    // ---- prologue: issue stages 0 and 1 ----
    #pragma unroll
    for (int s = 0; s < 2; s++) {
        const uint32_t bb = base + s * BUF_STRIDE;
        #pragma unroll
        for (int i = 0; i < 4; i++) {
            const int idx = tid + i * 256;
            const int row = idx >> 3, ch = idx & 7;
            const size_t go = (size_t)row * N_INPUT + s * BK + ch * 8;
            const uint32_t so = swz(row, ch);
            cp16(bb + OFF_A + so, gA + go);
            cp16(bb + OFF_B + so, gB + go);
        }
        asm volatile("cp.async.commit_group;" ::: "memory");
    }

    int bufidx = 0;
    for (int s = 0; s < KSTAGES; s++) {
        if (s < KSTAGES - 2) {
            asm volatile("cp.async.wait_group 1;" ::: "memory");
        } else {
            asm volatile("cp.async.wait_group 0;" ::: "memory");
        }
        __syncthreads();

        if (s + 2 < KSTAGES) {
            int pi = bufidx + 2; if (pi >= NBUF) pi -= NBUF;
            const uint32_t bb = base + pi * BUF_STRIDE;
            #pragma unroll
            for (int i = 0; i < 4; i++) {
                const int idx = tid + i * 256;
                const int row = idx >> 3, ch = idx & 7;
                const size_t go = (size_t)row * N_INPUT + (s + 2) * BK + ch * 8;
                const uint32_t so = swz(row, ch);
                cp16(bb + OFF_A + so, gA + go);
                cp16(bb + OFF_B + so, gB + go);
            }
            asm volatile("cp.async.commit_group;" ::: "memory");
        }

        const uint32_t cb = base + bufidx * BUF_STRIDE;
        uint32_t ah[2][2][4], bh[2][8][2];
        LOAD_FRAGS(0, ah[0], bh[0]);
        #pragma unroll
        for (int ks = 0; ks < 4; ks++) {
            const int cur = ks & 1, nxt = cur ^ 1;
            if (ks < 3) {
                LOAD_FRAGS(ks + 1, ah[nxt], bh[nxt]);
            }
            #pragma unroll
            for (int mt = 0; mt < 2; mt++)
                #pragma unroll
                for (int nt = 0; nt < 8; nt++)
                    mma_fp16(acc[mt][nt], ah[cur][mt], bh[cur][nt]);
        }

        bufidx++; if (bufidx >= NBUF) bufidx -= NBUF;
    }

    // ---- epilogue: bias + relu, float2 stores ----
    const int gq = lane >> 2, tq = lane & 3;
    #pragma unroll
    for (int mt = 0; mt < 2; mt++) {
        const int r0 = warp_m * 32 + mt * 16 + gq;
        float* crow0 = C + ((size_t)by * BM + r0) * UNITS + bx * BN;
        float* crow1 = crow0 + 8 * UNITS;
        #pragma unroll
        for (int nt = 0; nt < 8; nt++) {
            const int col = warp_n * 64 + nt * 8 + tq * 2;
            float2 o0, o1;
            o0.x = fmaxf(acc[mt][nt][0] + sbias[col], 0.0f);
            o0.y = fmaxf(acc[mt][nt][1] + sbias[col + 1], 0.0f);
            o1.x = fmaxf(acc[mt][nt][2] + sbias[col], 0.0f);
            o1.y = fmaxf(acc[mt][nt][3] + sbias[col + 1], 0.0f);
            *(float2*)(crow0 + col) = o0;
            *(float2*)(crow1 + col) = o1;
        }
    }
}

extern "C" void kernel_launch(void* const* d_in, const int* in_sizes, int n_in,
                              void* d_out, int out_size) {
    const float* x   = (const float*)d_in[0];
    const float* w   = (const float*)d_in[1];
    const float* b   = (const float*)d_in[2];
    const float* old = (const float*)d_in[3];
    const float* ind = (const float*)d_in[4];
    const int*   bc  = (const int*)d_in[5];

    const int M = in_sizes[0] / N_INPUT;

    cudaFuncSetAttribute(gemm_kernel, cudaFuncAttributeMaxDynamicSharedMemorySize, SMEM_DYN);

    const int n8 = M * N_INPUT / 8;
    const int xblocks = (n8 + 255) / 256;
    k1_kernel<<<N_DOP + xblocks, 256>>>(w, old, ind, bc, x, n8);
    prep_b_kernel<<<1, UNITS>>>();
    dim3 tgrid(UNITS / 32, N_INPUT / 32);
    prep2_kernel<<<tgrid, dim3(32, 32)>>>(w);
    dim3 grid(UNITS / BN, M / BM);
    gemm_kernel<<<grid, THREADS, SMEM_DYN>>>(b, (float*)d_out);
}